// round 8
// baseline (speedup 1.0000x reference)
#include <cuda_runtime.h>

#define EPSBN 1e-5f
#define ALPHA 0.2f

typedef unsigned long long ull;

static constexpr int B = 16, N = 4096, P = 1024, S = 32;
static constexpr int NTILES = (B * P) / 4;   // 4096 tiles, 4 groups each
static constexpr int OUT2_OFF = B * 3 * P;   // 49152

// fused transposed features: [b][n][0..2]=xyz, [3..66]=points, [67]=0
__device__ __align__(16) float g_xpt[(size_t)B * N * 68];
// a transposed to k-major: g_aT[d*132 + k] = a[3+k][d] (k<128),
// cols 128..130 = a[0..2][d] (xyz part), col 131 = 0
__device__ __align__(16) float g_aT[128 * 132];

// ---------------------------------------------------------------------------
// packed f32x2 helpers
// ---------------------------------------------------------------------------
__device__ __forceinline__ void ffma2(ull& d, ull a, ull b) {
    asm("fma.rn.f32x2 %0, %1, %2, %0;" : "+l"(d) : "l"(a), "l"(b));
}
__device__ __forceinline__ float hsum2(ull v) {
    float lo, hi;
    asm("mov.b64 {%0, %1}, %2;" : "=f"(lo), "=f"(hi) : "l"(v));
    return lo + hi;
}

// ---------------------------------------------------------------------------
// Kernel 1: transpose (B,3,N)+(B,64,N) channel-major -> (B,N,68) row-major
// ---------------------------------------------------------------------------
__global__ void __launch_bounds__(256) transpose_kernel(
    const float* __restrict__ xyz, const float* __restrict__ pts)
{
    __shared__ float sm[67 * 65];
    int b  = blockIdx.x >> 6;
    int n0 = (blockIdx.x & 63) << 6;
    int t  = threadIdx.x;
    for (int idx = t; idx < 67 * 64; idx += 256) {
        int c = idx >> 6, i = idx & 63;
        float v = (c < 3) ? xyz[(b * 3 + c) * N + n0 + i]
                          : pts[(b * 64 + (c - 3)) * N + n0 + i];
        sm[c * 65 + i] = v;
    }
    __syncthreads();
    for (int idx = t; idx < 64 * 17; idx += 256) {
        int row = idx / 17, c4 = idx % 17;
        int cb = c4 << 2;
        float4 v;
        v.x = sm[(cb + 0) * 65 + row];
        v.y = sm[(cb + 1) * 65 + row];
        v.z = sm[(cb + 2) * 65 + row];
        v.w = (cb + 3 < 67) ? sm[(cb + 3) * 65 + row] : 0.f;
        *(float4*)&g_xpt[((size_t)(b * N + n0 + row)) * 68 + cb] = v;
    }
}

// ---------------------------------------------------------------------------
// Kernel 2: transpose 'a' to k-major (d rows, stride 132)
// ---------------------------------------------------------------------------
__global__ void __launch_bounds__(256) prep_kernel(const float* __restrict__ aG)
{
    int j = blockIdx.x * 256 + threadIdx.x;
    if (j < 128 * 132) {
        int d = j / 132, k = j % 132;
        float val;
        if (k < 128)       val = aG[(3 + k) * 128 + d];
        else if (k < 131)  val = aG[(k - 128) * 128 + d];
        else               val = 0.f;
        g_aT[j] = val;
    }
}

// ---------------------------------------------------------------------------
// MLP GEMM (f32x2 packed over K, compile-time K4, unroll 4):
// out[r][d] = relu(sum_k in[r][k]*W[d][k] + bias[d]); strides 68/68.
// ---------------------------------------------------------------------------
template<int K4>
__device__ __forceinline__ void gemm_relu2(
    const float* __restrict__ sIn, const float* __restrict__ sW,
    const float* __restrict__ sBias, float* __restrict__ sOut,
    int outStride, int dOff, int t)
{
    int d_blk = t & 7;
    int rb0   = t >> 3;
    for (int rb = rb0; rb < 33; rb += 32) {
        int r0 = rb << 2;
        ull acc[4][8];
#pragma unroll
        for (int i = 0; i < 4; i++)
#pragma unroll
            for (int j = 0; j < 8; j++) acc[i][j] = 0ull;
#pragma unroll 4
        for (int k4 = 0; k4 < K4; k4++) {
            ulonglong2 xv[4];
#pragma unroll
            for (int i = 0; i < 4; i++)
                xv[i] = *(const ulonglong2*)&sIn[(r0 + i) * 68 + (k4 << 2)];
#pragma unroll
            for (int j = 0; j < 8; j++) {
                ulonglong2 wv = *(const ulonglong2*)&sW[(dOff + d_blk + (j << 3)) * 68 + (k4 << 2)];
#pragma unroll
                for (int i = 0; i < 4; i++) {
                    ffma2(acc[i][j], xv[i].x, wv.x);
                    ffma2(acc[i][j], xv[i].y, wv.y);
                }
            }
        }
#pragma unroll
        for (int j = 0; j < 8; j++) {
            int d = dOff + d_blk + (j << 3);
            float bb = sBias[d];
#pragma unroll
            for (int i = 0; i < 4; i++) {
                float v = hsum2(acc[i][j]) + bb;
                sOut[(r0 + i) * outStride + d] = v > 0.f ? v : 0.f;
            }
        }
    }
}

// ---------------------------------------------------------------------------
// E-GEMM half: E[r][dl] = H3[r] . aTh[dl]  (K=128, dl in 0..63)
// sIn stride 132 (H3), sW stride 132 (aT half), sOut stride 68 (X region)
// ---------------------------------------------------------------------------
__device__ __forceinline__ void gemm_e(
    const float* __restrict__ sIn, const float* __restrict__ sW,
    float* __restrict__ sOut, int t)
{
    int d_blk = t & 7;
    int rb0   = t >> 3;
    for (int rb = rb0; rb < 33; rb += 32) {
        int r0 = rb << 2;
        ull acc[4][8];
#pragma unroll
        for (int i = 0; i < 4; i++)
#pragma unroll
            for (int j = 0; j < 8; j++) acc[i][j] = 0ull;
#pragma unroll 4
        for (int k4 = 0; k4 < 32; k4++) {
            ulonglong2 xv[4];
#pragma unroll
            for (int i = 0; i < 4; i++)
                xv[i] = *(const ulonglong2*)&sIn[(r0 + i) * 132 + (k4 << 2)];
#pragma unroll
            for (int j = 0; j < 8; j++) {
                ulonglong2 wv = *(const ulonglong2*)&sW[(d_blk + (j << 3)) * 132 + (k4 << 2)];
#pragma unroll
                for (int i = 0; i < 4; i++) {
                    ffma2(acc[i][j], xv[i].x, wv.x);
                    ffma2(acc[i][j], xv[i].y, wv.y);
                }
            }
        }
#pragma unroll
        for (int j = 0; j < 8; j++) {
            int dl = d_blk + (j << 3);
#pragma unroll
            for (int i = 0; i < 4; i++)
                sOut[(r0 + i) * 68 + dl] = hsum2(acc[i][j]);
        }
    }
}

// ---------------------------------------------------------------------------
// Main fused kernel: persistent CTAs, each tile = 4 groups (132 rows)
// smem layout (floats):
//  W1s 0(4352) W2s 4352(4352) W3s 8704(8704) c1 17408(64) c2 17472(64)
//  c3 17536(128) X 17664(8976) H1 26640(8976) H3 35616(17424)
//  relx 53040(384) nX 53424(16) rowGi 53440(132) -> 53572 floats
// During attention: aT-half (64x132=8448) lives in H1; E-half (132x68=8976)
// lives in X. Weights stay resident the whole kernel.
// ---------------------------------------------------------------------------
__global__ void __launch_bounds__(256, 1) main_kernel(
    const int* __restrict__ fpsIdx, const int* __restrict__ grpIdx,
    const float* __restrict__ w1, const float* __restrict__ b1,
    const float* __restrict__ g1, const float* __restrict__ bt1,
    const float* __restrict__ m1, const float* __restrict__ v1,
    const float* __restrict__ w2, const float* __restrict__ b2,
    const float* __restrict__ g2, const float* __restrict__ bt2,
    const float* __restrict__ m2, const float* __restrict__ v2,
    const float* __restrict__ w3, const float* __restrict__ b3,
    const float* __restrict__ g3, const float* __restrict__ bt3,
    const float* __restrict__ m3, const float* __restrict__ v3,
    float* __restrict__ out)
{
    extern __shared__ float sm[];
    float* W1s  = sm;
    float* W2s  = sm + 4352;
    float* W3s  = sm + 8704;
    float* c1s  = sm + 17408;
    float* c2s  = sm + 17472;
    float* c3s  = sm + 17536;
    float* X    = sm + 17664;   // E-half during attention
    float* H1   = sm + 26640;   // aT-half during attention
    float* H3   = sm + 35616;
    float* relx = sm + 53040;
    float* nX   = sm + 53424;
    int*  rowGi = (int*)(sm + 53440);

    int t = threadIdx.x;

    // fold BN into weights (once per CTA, resident whole kernel)
    for (int idx = t; idx < 64 * 68; idx += 256) {
        int d = idx / 68, k = idx % 68;
        float s1 = g1[d] * rsqrtf(v1[d] + EPSBN);
        float s2 = g2[d] * rsqrtf(v2[d] + EPSBN);
        W1s[idx] = (k < 67) ? w1[d * 67 + k] * s1 : 0.f;
        W2s[idx] = (k < 64) ? w2[d * 64 + k] * s2 : 0.f;
    }
    for (int idx = t; idx < 128 * 68; idx += 256) {
        int d = idx / 68, k = idx % 68;
        float s3 = g3[d] * rsqrtf(v3[d] + EPSBN);
        W3s[idx] = (k < 64) ? w3[d * 64 + k] * s3 : 0.f;
    }
    if (t < 64) {
        float s1 = g1[t] * rsqrtf(v1[t] + EPSBN);
        float s2 = g2[t] * rsqrtf(v2[t] + EPSBN);
        c1s[t] = (b1[t] - m1[t]) * s1 + bt1[t];
        c2s[t] = (b2[t] - m2[t]) * s2 + bt2[t];
    }
    if (t < 128) {
        float s3 = g3[t] * rsqrtf(v3[t] + EPSBN);
        c3s[t] = (b3[t] - m3[t]) * s3 + bt3[t];
    }

    for (int tile = blockIdx.x; tile < NTILES; tile += gridDim.x) {
        __syncthreads();                       // protect smem from prev tile
        int b  = tile >> 8;
        int p0 = (tile & 255) << 2;

        if (t < 132) {
            int gi;
            if (t < 128) gi = grpIdx[((b * P + p0 + (t >> 5)) << 5) + (t & 31)];
            else         gi = fpsIdx[b * P + p0 + (t - 128)];
            rowGi[t] = gi;
        }
        __syncthreads();
        if (t < 12) {
            int p = t / 3, c = t % 3;
            float v = g_xpt[((size_t)(b * N + rowGi[128 + p])) * 68 + c];
            nX[p * 4 + c] = v;
            out[(b * 3 + c) * P + p0 + p] = v;   // new_xyz output (B,3,P)
        }
        __syncthreads();

        // gather 132 feature rows (67 valid floats each)
        for (int idx = t; idx < 132 * 17; idx += 256) {
            int row = idx / 17, c4 = idx % 17;
            float4 v = *(const float4*)&g_xpt[((size_t)(b * N + rowGi[row])) * 68 + (c4 << 2)];
            if (c4 == 0 && row < 128) {          // relative xyz for neighbor rows
                int p = row >> 5;
                v.x -= nX[p * 4 + 0];
                v.y -= nX[p * 4 + 1];
                v.z -= nX[p * 4 + 2];
                relx[row * 3 + 0] = v.x;
                relx[row * 3 + 1] = v.y;
                relx[row * 3 + 2] = v.z;
            }
            *(float4*)&X[row * 68 + (c4 << 2)] = v;
        }
        __syncthreads();

        gemm_relu2<17>(X,  W1s, c1s, H1, 68,  0,  t);   // 67 -> 64
        __syncthreads();
        gemm_relu2<16>(H1, W2s, c2s, X,  68,  0,  t);   // 64 -> 64 (H2 in X)
        __syncthreads();

        // H1 dead now: prefetch aT half 0 into H1 while layer-3 runs
        for (int idx = t; idx < (64 * 132) / 4; idx += 256)
            *(float4*)&H1[idx << 2] = *(const float4*)&g_aT[idx << 2];

        gemm_relu2<16>(X,  W3s, c3s, H3, 132, 0,  t);   // 64 -> 128
        gemm_relu2<16>(X,  W3s, c3s, H3, 132, 64, t);
        __syncthreads();

        // attention, channel-half at a time
#pragma unroll
        for (int h = 0; h < 2; h++) {
            // E[r][dl] = H3[r] . aT[h*64+dl]  -> X (stride 68)
            gemm_e(H3, H1, X, t);
            __syncthreads();

            // softmax + pool: 256 threads = 4 pl x 64 dl columns.
            // Concurrently: copy aT half 1 into H1 (only when h==0; softmax
            // no longer reads H1 -- xyz coeffs come from g_aT via LDG).
            if (h == 0) {
                for (int idx = t; idx < (64 * 132) / 4; idx += 256)
                    *(float4*)&H1[idx << 2] =
                        *(const float4*)&g_aT[(64 * 132) + (idx << 2)];
            }
            {
                int pl = t >> 6;                  // local group 0..3
                int dl = t & 63;
                int d  = (h << 6) + dl;           // global channel
                float Fpd = X[(128 + pl) * 68 + dl];
                float av0 = g_aT[d * 132 + 128];
                float av1 = g_aT[d * 132 + 129];
                float av2 = g_aT[d * 132 + 130];
                float nx0 = nX[pl * 4 + 0], nx1 = nX[pl * 4 + 1], nx2 = nX[pl * 4 + 2];
                float ev_arr[32];
                float mx = -1e30f;
#pragma unroll
                for (int r = 0; r < 32; r++) {
                    int row = (pl << 5) + r;
                    float ev = Fpd - X[row * 68 + dl]
                        + (nx0 - relx[row * 3 + 0]) * av0
                        + (nx1 - relx[row * 3 + 1]) * av1
                        + (nx2 - relx[row * 3 + 2]) * av2;
                    ev = ev > 0.f ? ev : ALPHA * ev;      // leaky relu
                    ev_arr[r] = ev;
                    mx = fmaxf(mx, ev);
                }
                float ssum = 0.f;
                float pooled = 0.f;
#pragma unroll
                for (int r = 0; r < 32; r++) {
                    float ee = __expf(ev_arr[r] - mx);
                    ssum += ee;
                    pooled += ee * H3[((pl << 5) + r) * 132 + d];
                }
                out[OUT2_OFF + (b * 128 + d) * P + p0 + pl] = pooled / ssum;
            }
            __syncthreads();
        }
    }
}

// ---------------------------------------------------------------------------
extern "C" void kernel_launch(void* const* d_in, const int* in_sizes, int n_in,
                              void* d_out, int out_size) {
    const float* xyz    = (const float*)d_in[0];
    const float* pts    = (const float*)d_in[1];
    const int*   fpsIdx = (const int*)d_in[2];
    const int*   grpIdx = (const int*)d_in[3];
    const float* w1 = (const float*)d_in[4];
    const float* b1 = (const float*)d_in[5];
    const float* g1 = (const float*)d_in[6];
    const float* bt1 = (const float*)d_in[7];
    const float* m1 = (const float*)d_in[8];
    const float* v1 = (const float*)d_in[9];
    const float* w2 = (const float*)d_in[10];
    const float* b2 = (const float*)d_in[11];
    const float* g2 = (const float*)d_in[12];
    const float* bt2 = (const float*)d_in[13];
    const float* m2 = (const float*)d_in[14];
    const float* v2 = (const float*)d_in[15];
    const float* w3 = (const float*)d_in[16];
    const float* b3 = (const float*)d_in[17];
    const float* g3 = (const float*)d_in[18];
    const float* bt3 = (const float*)d_in[19];
    const float* m3 = (const float*)d_in[20];
    const float* v3 = (const float*)d_in[21];
    const float* aG = (const float*)d_in[22];
    float* out = (float*)d_out;

    transpose_kernel<<<1024, 256>>>(xyz, pts);
    prep_kernel<<<(128 * 132 + 255) / 256, 256>>>(aG);

    const int smBytes = 53572 * 4;   // 214288 B
    cudaFuncSetAttribute(main_kernel,
                         cudaFuncAttributeMaxDynamicSharedMemorySize, smBytes);
    int smCount = 148;
    cudaDeviceGetAttribute(&smCount, cudaDevAttrMultiProcessorCount, 0);

    main_kernel<<<smCount, 256, smBytes>>>(
        fpsIdx, grpIdx,
        w1, b1, g1, bt1, m1, v1,
        w2, b2, g2, bt2, m2, v2,
        w3, b3, g3, bt3, m3, v3,
        out);
}